// round 2
// baseline (speedup 1.0000x reference)
#include <cuda_runtime.h>

#define HDIM 256
#define MAX_E 200000
#define MAX_N 50000

// ---------------- static scratch (no allocations allowed) ----------------
__device__ float g_msg_input[MAX_E * HDIM];   // pre-activation edge input
__device__ float g_msg[MAX_E * HDIM];         // current message (post-relu)
__device__ float g_tmp[MAX_E * HDIM];         // accum + edge_alpha (GEMM A operand)
__device__ float g_node_alpha[MAX_N * HDIM];
__device__ float g_m[MAX_N * HDIM];
__device__ float g_h[MAX_N * HDIM];
__device__ int   g_row_ptr[MAX_E + 1];

// ---------------- small utility kernels ----------------
__global__ void k_zero_alpha(int n) {
    int i = blockIdx.x * blockDim.x + threadIdx.x;
    if (i < n) g_node_alpha[i] = 0.f;
}

__global__ void k_build_ptr(const int* __restrict__ lg_dst, int L, int E) {
    int e = blockIdx.x * blockDim.x + threadIdx.x;
    if (e > E) return;
    int lo = 0, hi = L;                       // lower_bound of e in sorted lg_dst
    while (lo < hi) { int mid = (lo + hi) >> 1; if (lg_dst[mid] < e) lo = mid + 1; else hi = mid; }
    g_row_ptr[e] = lo;
}

__global__ void k_scatter_alpha(const float* __restrict__ tree_m,
                                const int* __restrict__ tgt,
                                const int* __restrict__ teid, int K) {
    int i = blockIdx.x * blockDim.x + threadIdx.x;
    int k = i >> 8, h = i & 255;
    if (k >= K) return;
    atomicAdd(&g_node_alpha[tgt[k] * HDIM + h], tree_m[teid[k] * HDIM + h]);
}

__global__ void k_copy_alpha_to_m(int n) {
    int i = blockIdx.x * blockDim.x + threadIdx.x;
    if (i < n) g_m[i] = g_node_alpha[i];
}

__global__ void k_scatter_m(const int* __restrict__ edst, int E) {
    int i = blockIdx.x * blockDim.x + threadIdx.x;   // i = e*256 + h
    int e = i >> 8, h = i & 255;
    if (e >= E) return;
    atomicAdd(&g_m[edst[e] * HDIM + h], g_msg[i]);
}

// tmp[e] = node_alpha[src[e]] + sum_{lg in-edges of e} msg[lg_src]
__global__ void k_gather(const int* __restrict__ esrc, const int* __restrict__ lg_src, int E) {
    __shared__ int sl[256];
    int e = blockIdx.x;
    int t = threadIdx.x;
    int s  = g_row_ptr[e];
    int en = g_row_ptr[e + 1];
    float acc = g_node_alpha[esrc[e] * HDIM + t];
    for (int base = s; base < en; base += 256) {
        int nn = min(256, en - base);
        __syncthreads();
        if (t < nn) sl[t] = lg_src[base + t];
        __syncthreads();
        for (int i = 0; i < nn; i++)
            acc += g_msg[sl[i] * HDIM + t];
    }
    g_tmp[e * HDIM + t] = acc;
}

// ---------------- GEMM kernels: BM=64, BN=256, BK=8, 256 thr, 8x8 microtile ----------------

#define GEMM_FMA_BLOCK()                                            \
    _Pragma("unroll")                                               \
    for (int kk = 0; kk < 8; kk++) {                                \
        float4 a0 = *(float4*)&As[kk][rm];                          \
        float4 a1 = *(float4*)&As[kk][rm + 4];                      \
        float4 b0 = *(float4*)&Bs[kk][cn];                          \
        float4 b1 = *(float4*)&Bs[kk][cn + 4];                      \
        float a[8] = {a0.x,a0.y,a0.z,a0.w,a1.x,a1.y,a1.z,a1.w};     \
        float b[8] = {b0.x,b0.y,b0.z,b0.w,b1.x,b1.y,b1.z,b1.w};     \
        _Pragma("unroll")                                           \
        for (int ii = 0; ii < 8; ii++)                              \
            _Pragma("unroll")                                       \
            for (int jj = 0; jj < 8; jj++)                          \
                acc[ii][jj] += a[ii] * b[jj];                       \
    }

// msg_input = [x_nodes[src] | x_edges] @ W_i ; msg = relu(msg_input)
__global__ __launch_bounds__(256, 2)
void k_edge_input(const float* __restrict__ x_nodes, const float* __restrict__ x_edges,
                  const float* __restrict__ W_i, const int* __restrict__ esrc, int E) {
    __shared__ float As[8][64];
    __shared__ float Bs[8][256];
    int tid = threadIdx.x;
    int row0 = blockIdx.x * 64;
    int rm = (tid >> 5) * 8, cn = (tid & 31) * 8;
    float acc[8][8] = {};
    for (int kt = 0; kt < 5; kt++) {            // K = 40
        int k0 = kt * 8;
#pragma unroll
        for (int u = 0; u < 2; u++) {
            int li = tid * 2 + u;
            int r = li >> 3, kk = li & 7;
            int row = row0 + r, gk = k0 + kk;
            float v = 0.f;
            if (row < E)
                v = (gk < 35) ? x_nodes[esrc[row] * 35 + gk] : x_edges[row * 5 + (gk - 35)];
            As[kk][r] = v;
        }
#pragma unroll
        for (int u = 0; u < 2; u++) {
            int li4 = tid * 2 + u;
            int kk = li4 >> 6, n4 = li4 & 63;
            *(float4*)&Bs[kk][n4 * 4] = *(const float4*)&W_i[(k0 + kk) * 256 + n4 * 4];
        }
        __syncthreads();
        GEMM_FMA_BLOCK();
        __syncthreads();
    }
#pragma unroll
    for (int i = 0; i < 8; i++) {
        int row = row0 + rm + i;
        if (row >= E) break;
        int base = row * HDIM + cn;
#pragma unroll
        for (int j = 0; j < 8; j++) {
            float v = acc[i][j];
            g_msg_input[base + j] = v;
            g_msg[base + j] = fmaxf(v, 0.f);
        }
    }
}

// msg = relu(msg_input + tmp @ W_h)
__global__ __launch_bounds__(256, 2)
void k_bp_gemm(const float* __restrict__ W_h, int E) {
    __shared__ float As[8][64];
    __shared__ float Bs[8][256];
    int tid = threadIdx.x;
    int row0 = blockIdx.x * 64;
    int rm = (tid >> 5) * 8, cn = (tid & 31) * 8;
    float acc[8][8] = {};
    for (int kt = 0; kt < 32; kt++) {           // K = 256
        int k0 = kt * 8;
#pragma unroll
        for (int u = 0; u < 2; u++) {
            int li = tid * 2 + u;
            int r = li >> 3, kk = li & 7;
            int row = row0 + r;
            As[kk][r] = (row < E) ? g_tmp[row * HDIM + k0 + kk] : 0.f;
        }
#pragma unroll
        for (int u = 0; u < 2; u++) {
            int li4 = tid * 2 + u;
            int kk = li4 >> 6, n4 = li4 & 63;
            *(float4*)&Bs[kk][n4 * 4] = *(const float4*)&W_h[(k0 + kk) * 256 + n4 * 4];
        }
        __syncthreads();
        GEMM_FMA_BLOCK();
        __syncthreads();
    }
#pragma unroll
    for (int i = 0; i < 8; i++) {
        int row = row0 + rm + i;
        if (row >= E) break;
        int base = row * HDIM + cn;
#pragma unroll
        for (int j4 = 0; j4 < 2; j4++) {
            float4 mi = *(float4*)&g_msg_input[base + j4 * 4];
            float4 o;
            o.x = fmaxf(mi.x + acc[i][j4 * 4 + 0], 0.f);
            o.y = fmaxf(mi.y + acc[i][j4 * 4 + 1], 0.f);
            o.z = fmaxf(mi.z + acc[i][j4 * 4 + 2], 0.f);
            o.w = fmaxf(mi.w + acc[i][j4 * 4 + 3], 0.f);
            *(float4*)&g_msg[base + j4 * 4] = o;
        }
    }
}

// h = relu([x_nodes | m] @ W_o + b_o)
__global__ __launch_bounds__(256, 2)
void k_out(const float* __restrict__ x_nodes, const float* __restrict__ W_o,
           const float* __restrict__ b_o, int N) {
    __shared__ float As[8][64];
    __shared__ float Bs[8][256];
    int tid = threadIdx.x;
    int row0 = blockIdx.x * 64;
    int rm = (tid >> 5) * 8, cn = (tid & 31) * 8;
    float acc[8][8] = {};
    for (int kt = 0; kt < 37; kt++) {           // K = 291, padded to 296
        int k0 = kt * 8;
#pragma unroll
        for (int u = 0; u < 2; u++) {
            int li = tid * 2 + u;
            int r = li >> 3, kk = li & 7;
            int row = row0 + r, gk = k0 + kk;
            float v = 0.f;
            if (row < N && gk < 291)
                v = (gk < 35) ? x_nodes[row * 35 + gk] : g_m[row * 256 + (gk - 35)];
            As[kk][r] = v;
        }
#pragma unroll
        for (int u = 0; u < 2; u++) {
            int li4 = tid * 2 + u;
            int kk = li4 >> 6, n4 = li4 & 63;
            int gk = k0 + kk;
            float4 bv = make_float4(0.f, 0.f, 0.f, 0.f);
            if (gk < 291) bv = *(const float4*)&W_o[gk * 256 + n4 * 4];
            *(float4*)&Bs[kk][n4 * 4] = bv;
        }
        __syncthreads();
        GEMM_FMA_BLOCK();
        __syncthreads();
    }
#pragma unroll
    for (int i = 0; i < 8; i++) {
        int row = row0 + rm + i;
        if (row >= N) break;
        int base = row * HDIM + cn;
#pragma unroll
        for (int j = 0; j < 8; j++)
            g_h[base + j] = fmaxf(acc[i][j] + b_o[cn + j], 0.f);
    }
}

// per-graph mean over sorted graph_ids
__global__ void k_mean(const int* __restrict__ gid, float* __restrict__ out, int N) {
    int g = blockIdx.x;
    int t = threadIdx.x;
    int lo = 0, hi = N;
    while (lo < hi) { int m = (lo + hi) >> 1; if (gid[m] < g) lo = m + 1; else hi = m; }
    int s = lo;
    hi = N;
    while (lo < hi) { int m = (lo + hi) >> 1; if (gid[m] < g + 1) lo = m + 1; else hi = m; }
    int e = lo;
    float sum = 0.f;
    for (int n = s; n < e; n++) sum += g_h[n * HDIM + t];
    float c = (float)((e - s) > 0 ? (e - s) : 1);
    out[g * HDIM + t] = sum / c;
}

// ---------------- launcher ----------------
extern "C" void kernel_launch(void* const* d_in, const int* in_sizes, int n_in,
                              void* d_out, int out_size) {
    const float* x_nodes = (const float*)d_in[0];
    const float* x_edges = (const float*)d_in[1];
    const float* tree_m  = (const float*)d_in[2];
    const float* W_i     = (const float*)d_in[3];
    const float* W_h     = (const float*)d_in[4];
    const float* W_o     = (const float*)d_in[5];
    const float* b_o     = (const float*)d_in[6];
    const int*   esrc    = (const int*)d_in[7];
    const int*   edst    = (const int*)d_in[8];
    const int*   lg_src  = (const int*)d_in[9];
    const int*   lg_dst  = (const int*)d_in[10];
    const int*   tgt     = (const int*)d_in[11];
    const int*   teid    = (const int*)d_in[12];
    const int*   gid     = (const int*)d_in[13];

    int N = in_sizes[0] / 35;
    int E = in_sizes[1] / 5;
    int L = in_sizes[9];
    int K = in_sizes[11];
    int G = out_size / HDIM;
    float* out = (float*)d_out;

    k_zero_alpha<<<(N * HDIM + 255) / 256, 256>>>(N * HDIM);
    k_build_ptr<<<(E + 1 + 255) / 256, 256>>>(lg_dst, L, E);
    k_edge_input<<<(E + 63) / 64, 256>>>(x_nodes, x_edges, W_i, esrc, E);
    k_scatter_alpha<<<(K * 256 + 255) / 256, 256>>>(tree_m, tgt, teid, K);

    for (int it = 0; it < 3; it++) {            // DEPTH-1
        k_gather<<<E, 256>>>(esrc, lg_src, E);
        k_bp_gemm<<<(E + 63) / 64, 256>>>(W_h, E);
    }

    k_copy_alpha_to_m<<<(N * HDIM + 255) / 256, 256>>>(N * HDIM);
    k_scatter_m<<<(E * 256 + 255) / 256, 256>>>(edst, E);
    k_out<<<(N + 63) / 64, 256>>>(x_nodes, W_o, b_o, N);
    k_mean<<<G, 256>>>(gid, out, N);
}

// round 3
// speedup vs baseline: 1.5362x; 1.5362x over previous
#include <cuda_runtime.h>

#define HDIM 256
#define MAX_E 200000
#define MAX_N 50000

// ---------------- static scratch (no allocations allowed) ----------------
__device__ float g_msg_input[MAX_E * HDIM];   // pre-activation edge input
__device__ float g_msg[MAX_E * HDIM];         // current message (post-relu)
__device__ float g_tmp[MAX_E * HDIM];         // accum + edge_alpha (GEMM A operand)
__device__ float g_node_alpha[MAX_N * HDIM];
__device__ float g_m[MAX_N * HDIM];
__device__ float g_h[MAX_N * HDIM];
__device__ int   g_row_ptr[MAX_E + 1];

// ---------------- helpers ----------------
__device__ __forceinline__ unsigned f2tf(float x) {
    unsigned u; asm("cvt.rna.tf32.f32 %0, %1;" : "=r"(u) : "f"(x)); return u;
}
__device__ __forceinline__ void mma_tf32(float* c, const unsigned* a, const unsigned* b) {
    asm volatile(
        "mma.sync.aligned.m16n8k8.row.col.f32.tf32.tf32.f32 "
        "{%0,%1,%2,%3}, {%4,%5,%6,%7}, {%8,%9}, {%0,%1,%2,%3};\n"
        : "+f"(c[0]), "+f"(c[1]), "+f"(c[2]), "+f"(c[3])
        : "r"(a[0]), "r"(a[1]), "r"(a[2]), "r"(a[3]), "r"(b[0]), "r"(b[1]));
}

// ---------------- small utility kernels ----------------
__global__ void k_zero_alpha(int n) {
    int i = blockIdx.x * blockDim.x + threadIdx.x;
    if (i < n) g_node_alpha[i] = 0.f;
}

__global__ void k_build_ptr(const int* __restrict__ lg_dst, int L, int E) {
    int e = blockIdx.x * blockDim.x + threadIdx.x;
    if (e > E) return;
    int lo = 0, hi = L;
    while (lo < hi) { int mid = (lo + hi) >> 1; if (lg_dst[mid] < e) lo = mid + 1; else hi = mid; }
    g_row_ptr[e] = lo;
}

__global__ void k_scatter_alpha(const float* __restrict__ tree_m,
                                const int* __restrict__ tgt,
                                const int* __restrict__ teid, int K) {
    int i = blockIdx.x * blockDim.x + threadIdx.x;
    int k = i >> 8, h = i & 255;
    if (k >= K) return;
    atomicAdd(&g_node_alpha[tgt[k] * HDIM + h], tree_m[teid[k] * HDIM + h]);
}

__global__ void k_copy_alpha_to_m(int n) {
    int i = blockIdx.x * blockDim.x + threadIdx.x;
    if (i < n) g_m[i] = g_node_alpha[i];
}

__global__ void k_scatter_m(const int* __restrict__ edst, int E) {
    int i = blockIdx.x * blockDim.x + threadIdx.x;
    int e = i >> 8, h = i & 255;
    if (e >= E) return;
    atomicAdd(&g_m[edst[e] * HDIM + h], g_msg[i]);
}

// tmp[e] = node_alpha[src[e]] + sum_{lg in-edges of e} msg[lg_src]
__global__ void k_gather(const int* __restrict__ esrc, const int* __restrict__ lg_src, int E) {
    __shared__ int sl[256];
    int e = blockIdx.x;
    int t = threadIdx.x;
    int s  = g_row_ptr[e];
    int en = g_row_ptr[e + 1];
    float acc = g_node_alpha[esrc[e] * HDIM + t];
    for (int base = s; base < en; base += 256) {
        int nn = min(256, en - base);
        __syncthreads();
        if (t < nn) sl[t] = lg_src[base + t];
        __syncthreads();
        for (int i = 0; i < nn; i++)
            acc += g_msg[sl[i] * HDIM + t];
    }
    g_tmp[e * HDIM + t] = acc;
}

// ---------------- edge-input GEMM (small K=40, SIMT) ----------------
#define GEMM_FMA_BLOCK()                                            \
    _Pragma("unroll")                                               \
    for (int kk = 0; kk < 8; kk++) {                                \
        float4 a0 = *(float4*)&As[kk][rm];                          \
        float4 a1 = *(float4*)&As[kk][rm + 4];                      \
        float4 b0 = *(float4*)&Bs[kk][cn];                          \
        float4 b1 = *(float4*)&Bs[kk][cn + 4];                      \
        float a[8] = {a0.x,a0.y,a0.z,a0.w,a1.x,a1.y,a1.z,a1.w};     \
        float b[8] = {b0.x,b0.y,b0.z,b0.w,b1.x,b1.y,b1.z,b1.w};     \
        _Pragma("unroll")                                           \
        for (int ii = 0; ii < 8; ii++)                              \
            _Pragma("unroll")                                       \
            for (int jj = 0; jj < 8; jj++)                          \
                acc[ii][jj] += a[ii] * b[jj];                       \
    }

__global__ __launch_bounds__(256, 2)
void k_edge_input(const float* __restrict__ x_nodes, const float* __restrict__ x_edges,
                  const float* __restrict__ W_i, const int* __restrict__ esrc, int E) {
    __shared__ float As[8][64];
    __shared__ float Bs[8][256];
    int tid = threadIdx.x;
    int row0 = blockIdx.x * 64;
    int rm = (tid >> 5) * 8, cn = (tid & 31) * 8;
    float acc[8][8] = {};
    for (int kt = 0; kt < 5; kt++) {
        int k0 = kt * 8;
#pragma unroll
        for (int u = 0; u < 2; u++) {
            int li = tid * 2 + u;
            int r = li >> 3, kk = li & 7;
            int row = row0 + r, gk = k0 + kk;
            float v = 0.f;
            if (row < E)
                v = (gk < 35) ? x_nodes[esrc[row] * 35 + gk] : x_edges[row * 5 + (gk - 35)];
            As[kk][r] = v;
        }
#pragma unroll
        for (int u = 0; u < 2; u++) {
            int li4 = tid * 2 + u;
            int kk = li4 >> 6, n4 = li4 & 63;
            *(float4*)&Bs[kk][n4 * 4] = *(const float4*)&W_i[(k0 + kk) * 256 + n4 * 4];
        }
        __syncthreads();
        GEMM_FMA_BLOCK();
        __syncthreads();
    }
#pragma unroll
    for (int i = 0; i < 8; i++) {
        int row = row0 + rm + i;
        if (row >= E) break;
        int base = row * HDIM + cn;
#pragma unroll
        for (int j = 0; j < 8; j++) {
            float v = acc[i][j];
            g_msg_input[base + j] = v;
            g_msg[base + j] = fmaxf(v, 0.f);
        }
    }
}

// ---------------- tf32 tensor-core GEMM: BM=64, BN=256, BK=16 ----------------
// 8 warps, warp tile 32x64 (2 m-tiles x 8 n-tiles of m16n8k8)

#define APAD 20
#define BPAD 264

// msg = relu(msg_input + tmp @ W_h)
__global__ __launch_bounds__(256)
void k_bp_tf32(const float* __restrict__ W_h, int E) {
    __shared__ unsigned As[2][64][APAD];
    __shared__ unsigned Bs[2][16][BPAD];
    int tid = threadIdx.x;
    int lane = tid & 31, wid = tid >> 5;
    int gg = lane >> 2, tig = lane & 3;
    int wm = (wid & 1) * 32, wn = (wid >> 1) * 64;
    long row0 = (long)blockIdx.x * 64;

    float c[2][8][4];
#pragma unroll
    for (int mt = 0; mt < 2; mt++)
#pragma unroll
        for (int nt = 0; nt < 8; nt++)
#pragma unroll
            for (int r = 0; r < 4; r++) c[mt][nt][r] = 0.f;

    // stage 0
    {
        int f = tid, row = f >> 2, c4 = f & 3;
        long r = row0 + row;
        float4 av = make_float4(0, 0, 0, 0);
        if (r < E) av = *(const float4*)&g_tmp[r * 256 + c4 * 4];
        unsigned* p = &As[0][row][c4 * 4];
        p[0] = f2tf(av.x); p[1] = f2tf(av.y); p[2] = f2tf(av.z); p[3] = f2tf(av.w);
#pragma unroll
        for (int u = 0; u < 4; u++) {
            int ff = tid + u * 256, krow = ff >> 6, cc = ff & 63;
            float4 bv = *(const float4*)&W_h[krow * 256 + cc * 4];
            unsigned* q = &Bs[0][krow][cc * 4];
            q[0] = f2tf(bv.x); q[1] = f2tf(bv.y); q[2] = f2tf(bv.z); q[3] = f2tf(bv.w);
        }
    }
    __syncthreads();

    for (int kt = 0; kt < 16; kt++) {
        int cbuf = kt & 1, nbuf = cbuf ^ 1;
        float4 av; float4 bv[4];
        if (kt < 15) {
            int k0 = (kt + 1) * 16;
            int f = tid, row = f >> 2, c4 = f & 3;
            long r = row0 + row;
            av = make_float4(0, 0, 0, 0);
            if (r < E) av = *(const float4*)&g_tmp[r * 256 + k0 + c4 * 4];
#pragma unroll
            for (int u = 0; u < 4; u++) {
                int ff = tid + u * 256, krow = ff >> 6, cc = ff & 63;
                bv[u] = *(const float4*)&W_h[(k0 + krow) * 256 + cc * 4];
            }
        }
        // compute current buffer
#pragma unroll
        for (int ks = 0; ks < 16; ks += 8) {
            unsigned a[2][4], b[8][2];
#pragma unroll
            for (int mt = 0; mt < 2; mt++) {
                int m0 = wm + mt * 16 + gg;
                a[mt][0] = As[cbuf][m0][ks + tig];
                a[mt][1] = As[cbuf][m0 + 8][ks + tig];
                a[mt][2] = As[cbuf][m0][ks + tig + 4];
                a[mt][3] = As[cbuf][m0 + 8][ks + tig + 4];
            }
#pragma unroll
            for (int nt = 0; nt < 8; nt++) {
                int n0 = wn + nt * 8 + gg;
                b[nt][0] = Bs[cbuf][ks + tig][n0];
                b[nt][1] = Bs[cbuf][ks + tig + 4][n0];
            }
#pragma unroll
            for (int mt = 0; mt < 2; mt++)
#pragma unroll
                for (int nt = 0; nt < 8; nt++)
                    mma_tf32(c[mt][nt], a[mt], b[nt]);
        }
        if (kt < 15) {
            int f = tid, row = f >> 2, c4 = f & 3;
            unsigned* p = &As[nbuf][row][c4 * 4];
            p[0] = f2tf(av.x); p[1] = f2tf(av.y); p[2] = f2tf(av.z); p[3] = f2tf(av.w);
#pragma unroll
            for (int u = 0; u < 4; u++) {
                int ff = tid + u * 256, krow = ff >> 6, cc = ff & 63;
                unsigned* q = &Bs[nbuf][krow][cc * 4];
                q[0] = f2tf(bv[u].x); q[1] = f2tf(bv[u].y); q[2] = f2tf(bv[u].z); q[3] = f2tf(bv[u].w);
            }
        }
        __syncthreads();
    }

    // epilogue: relu(msg_input + acc) -> msg
#pragma unroll
    for (int mt = 0; mt < 2; mt++) {
#pragma unroll
        for (int nt = 0; nt < 8; nt++) {
            int col = wn + nt * 8 + tig * 2;
            long r0 = row0 + wm + mt * 16 + gg;
            if (r0 < E) {
                float2 mi = *(const float2*)&g_msg_input[r0 * 256 + col];
                float2 o;
                o.x = fmaxf(mi.x + c[mt][nt][0], 0.f);
                o.y = fmaxf(mi.y + c[mt][nt][1], 0.f);
                *(float2*)&g_msg[r0 * 256 + col] = o;
            }
            long r1 = r0 + 8;
            if (r1 < E) {
                float2 mi = *(const float2*)&g_msg_input[r1 * 256 + col];
                float2 o;
                o.x = fmaxf(mi.x + c[mt][nt][2], 0.f);
                o.y = fmaxf(mi.y + c[mt][nt][3], 0.f);
                *(float2*)&g_msg[r1 * 256 + col] = o;
            }
        }
    }
}

// h = relu([x_nodes | m] @ W_o + b_o), K = 291 padded to 304 (19 tiles)
__global__ __launch_bounds__(256)
void k_out_tf32(const float* __restrict__ x_nodes, const float* __restrict__ W_o,
                const float* __restrict__ b_o, int N) {
    __shared__ unsigned As[2][64][APAD];
    __shared__ unsigned Bs[2][16][BPAD];
    int tid = threadIdx.x;
    int lane = tid & 31, wid = tid >> 5;
    int gg = lane >> 2, tig = lane & 3;
    int wm = (wid & 1) * 32, wn = (wid >> 1) * 64;
    long row0 = (long)blockIdx.x * 64;

    float c[2][8][4];
#pragma unroll
    for (int mt = 0; mt < 2; mt++)
#pragma unroll
        for (int nt = 0; nt < 8; nt++)
#pragma unroll
            for (int r = 0; r < 4; r++) c[mt][nt][r] = 0.f;

    const int NT = 19;   // 19*16 = 304 >= 291
    // stage 0
    {
#pragma unroll
        for (int u = 0; u < 4; u++) {
            int i = tid + u * 256;
            int row = i >> 4, kk = i & 15;
            long r = row0 + row; int gk = kk;
            float v = 0.f;
            if (r < N && gk < 291)
                v = (gk < 35) ? x_nodes[r * 35 + gk] : g_m[r * 256 + (gk - 35)];
            As[0][row][kk] = f2tf(v);
        }
#pragma unroll
        for (int u = 0; u < 4; u++) {
            int ff = tid + u * 256, krow = ff >> 6, cc = ff & 63;
            float4 bvv = make_float4(0, 0, 0, 0);
            if (krow < 291) bvv = *(const float4*)&W_o[krow * 256 + cc * 4];
            unsigned* q = &Bs[0][krow][cc * 4];
            q[0] = f2tf(bvv.x); q[1] = f2tf(bvv.y); q[2] = f2tf(bvv.z); q[3] = f2tf(bvv.w);
        }
    }
    __syncthreads();

    for (int kt = 0; kt < NT; kt++) {
        int cbuf = kt & 1, nbuf = cbuf ^ 1;
        float avs[4]; float4 bv[4];
        if (kt < NT - 1) {
            int k0 = (kt + 1) * 16;
#pragma unroll
            for (int u = 0; u < 4; u++) {
                int i = tid + u * 256;
                int row = i >> 4, kk = i & 15;
                long r = row0 + row; int gk = k0 + kk;
                float v = 0.f;
                if (r < N && gk < 291)
                    v = (gk < 35) ? x_nodes[r * 35 + gk] : g_m[r * 256 + (gk - 35)];
                avs[u] = v;
            }
#pragma unroll
            for (int u = 0; u < 4; u++) {
                int ff = tid + u * 256, krow = ff >> 6, cc = ff & 63;
                int gk = k0 + krow;
                bv[u] = make_float4(0, 0, 0, 0);
                if (gk < 291) bv[u] = *(const float4*)&W_o[gk * 256 + cc * 4];
            }
        }
#pragma unroll
        for (int ks = 0; ks < 16; ks += 8) {
            unsigned a[2][4], b[8][2];
#pragma unroll
            for (int mt = 0; mt < 2; mt++) {
                int m0 = wm + mt * 16 + gg;
                a[mt][0] = As[cbuf][m0][ks + tig];
                a[mt][1] = As[cbuf][m0 + 8][ks + tig];
                a[mt][2] = As[cbuf][m0][ks + tig + 4];
                a[mt][3] = As[cbuf][m0 + 8][ks + tig + 4];
            }
#pragma unroll
            for (int nt = 0; nt < 8; nt++) {
                int n0 = wn + nt * 8 + gg;
                b[nt][0] = Bs[cbuf][ks + tig][n0];
                b[nt][1] = Bs[cbuf][ks + tig + 4][n0];
            }
#pragma unroll
            for (int mt = 0; mt < 2; mt++)
#pragma unroll
                for (int nt = 0; nt < 8; nt++)
                    mma_tf32(c[mt][nt], a[mt], b[nt]);
        }
        if (kt < NT - 1) {
#pragma unroll
            for (int u = 0; u < 4; u++) {
                int i = tid + u * 256;
                int row = i >> 4, kk = i & 15;
                As[nbuf][row][kk] = f2tf(avs[u]);
            }
#pragma unroll
            for (int u = 0; u < 4; u++) {
                int ff = tid + u * 256, krow = ff >> 6, cc = ff & 63;
                unsigned* q = &Bs[nbuf][krow][cc * 4];
                q[0] = f2tf(bv[u].x); q[1] = f2tf(bv[u].y); q[2] = f2tf(bv[u].z); q[3] = f2tf(bv[u].w);
            }
        }
        __syncthreads();
    }

#pragma unroll
    for (int mt = 0; mt < 2; mt++) {
#pragma unroll
        for (int nt = 0; nt < 8; nt++) {
            int col = wn + nt * 8 + tig * 2;
            float b0v = b_o[col], b1v = b_o[col + 1];
            long r0 = row0 + wm + mt * 16 + gg;
            if (r0 < N) {
                float2 o;
                o.x = fmaxf(c[mt][nt][0] + b0v, 0.f);
                o.y = fmaxf(c[mt][nt][1] + b1v, 0.f);
                *(float2*)&g_h[r0 * 256 + col] = o;
            }
            long r1 = r0 + 8;
            if (r1 < N) {
                float2 o;
                o.x = fmaxf(c[mt][nt][2] + b0v, 0.f);
                o.y = fmaxf(c[mt][nt][3] + b1v, 0.f);
                *(float2*)&g_h[r1 * 256 + col] = o;
            }
        }
    }
}

// per-graph mean over sorted graph_ids
__global__ void k_mean(const int* __restrict__ gid, float* __restrict__ out, int N) {
    int g = blockIdx.x;
    int t = threadIdx.x;
    int lo = 0, hi = N;
    while (lo < hi) { int m = (lo + hi) >> 1; if (gid[m] < g) lo = m + 1; else hi = m; }
    int s = lo;
    hi = N;
    while (lo < hi) { int m = (lo + hi) >> 1; if (gid[m] < g + 1) lo = m + 1; else hi = m; }
    int e = lo;
    float sum = 0.f;
    for (int n = s; n < e; n++) sum += g_h[n * HDIM + t];
    float c = (float)((e - s) > 0 ? (e - s) : 1);
    out[g * HDIM + t] = sum / c;
}

// ---------------- launcher ----------------
extern "C" void kernel_launch(void* const* d_in, const int* in_sizes, int n_in,
                              void* d_out, int out_size) {
    const float* x_nodes = (const float*)d_in[0];
    const float* x_edges = (const float*)d_in[1];
    const float* tree_m  = (const float*)d_in[2];
    const float* W_i     = (const float*)d_in[3];
    const float* W_h     = (const float*)d_in[4];
    const float* W_o     = (const float*)d_in[5];
    const float* b_o     = (const float*)d_in[6];
    const int*   esrc    = (const int*)d_in[7];
    const int*   edst    = (const int*)d_in[8];
    const int*   lg_src  = (const int*)d_in[9];
    const int*   lg_dst  = (const int*)d_in[10];
    const int*   tgt     = (const int*)d_in[11];
    const int*   teid    = (const int*)d_in[12];
    const int*   gid     = (const int*)d_in[13];

    int N = in_sizes[0] / 35;
    int E = in_sizes[1] / 5;
    int L = in_sizes[9];
    int K = in_sizes[11];
    int G = out_size / HDIM;
    float* out = (float*)d_out;

    k_zero_alpha<<<(N * HDIM + 255) / 256, 256>>>(N * HDIM);
    k_build_ptr<<<(E + 1 + 255) / 256, 256>>>(lg_dst, L, E);
    k_edge_input<<<(E + 63) / 64, 256>>>(x_nodes, x_edges, W_i, esrc, E);
    k_scatter_alpha<<<(K * 256 + 255) / 256, 256>>>(tree_m, tgt, teid, K);

    for (int it = 0; it < 3; it++) {
        k_gather<<<E, 256>>>(esrc, lg_src, E);
        k_bp_tf32<<<(E + 63) / 64, 256>>>(W_h, E);
    }

    k_copy_alpha_to_m<<<(N * HDIM + 255) / 256, 256>>>(N * HDIM);
    k_scatter_m<<<(E * 256 + 255) / 256, 256>>>(edst, E);
    k_out_tf32<<<(N + 63) / 64, 256>>>(x_nodes, W_o, b_o, N);
    k_mean<<<G, 256>>>(gid, out, N);
}

// round 4
// speedup vs baseline: 2.4104x; 1.5691x over previous
#include <cuda_runtime.h>

#define HDIM 256
#define MAX_E 200000
#define MAX_N 50000

// ---------------- static scratch (no allocations allowed) ----------------
__device__ float g_msg_input[MAX_E * HDIM];
__device__ float g_msg[MAX_E * HDIM];
__device__ float g_tmp[MAX_E * HDIM];
__device__ float g_node_alpha[MAX_N * HDIM];
__device__ float g_m[MAX_N * HDIM];
__device__ float g_h[MAX_N * HDIM];
__device__ int   g_row_ptr[MAX_E + 1];

// ---------------- helpers ----------------
__device__ __forceinline__ unsigned f2tf(float x) {
    unsigned u; asm("cvt.rna.tf32.f32 %0, %1;" : "=r"(u) : "f"(x)); return u;
}
__device__ __forceinline__ void mma_tf32(float* c, const unsigned* a, const unsigned* b) {
    asm volatile(
        "mma.sync.aligned.m16n8k8.row.col.f32.tf32.tf32.f32 "
        "{%0,%1,%2,%3}, {%4,%5,%6,%7}, {%8,%9}, {%0,%1,%2,%3};\n"
        : "+f"(c[0]), "+f"(c[1]), "+f"(c[2]), "+f"(c[3])
        : "r"(a[0]), "r"(a[1]), "r"(a[2]), "r"(a[3]), "r"(b[0]), "r"(b[1]));
}

// ---------------- small utility kernels ----------------
__global__ void k_zero_alpha(int n) {
    int i = blockIdx.x * blockDim.x + threadIdx.x;
    if (i < n) g_node_alpha[i] = 0.f;
}

__global__ void k_build_ptr(const int* __restrict__ lg_dst, int L, int E) {
    int e = blockIdx.x * blockDim.x + threadIdx.x;
    if (e > E) return;
    int lo = 0, hi = L;
    while (lo < hi) { int mid = (lo + hi) >> 1; if (lg_dst[mid] < e) lo = mid + 1; else hi = mid; }
    g_row_ptr[e] = lo;
}

__global__ void k_scatter_alpha(const float* __restrict__ tree_m,
                                const int* __restrict__ tgt,
                                const int* __restrict__ teid, int K) {
    int i = blockIdx.x * blockDim.x + threadIdx.x;
    int k = i >> 8, h = i & 255;
    if (k >= K) return;
    atomicAdd(&g_node_alpha[tgt[k] * HDIM + h], tree_m[teid[k] * HDIM + h]);
}

__global__ void k_copy_alpha_to_m(int n) {
    int i = blockIdx.x * blockDim.x + threadIdx.x;
    if (i < n) g_m[i] = g_node_alpha[i];
}

__global__ void k_scatter_m(const int* __restrict__ edst, int E) {
    int i = blockIdx.x * blockDim.x + threadIdx.x;
    int e = i >> 8, h = i & 255;
    if (e >= E) return;
    atomicAdd(&g_m[edst[e] * HDIM + h], g_msg[i]);
}

// tmp[e] = node_alpha[src[e]] + sum_{lg in-edges of e} msg[lg_src]
// 4 edges per block, 64 threads (float4) per edge, 4-way batched loads for MLP
__global__ __launch_bounds__(256)
void k_gather(const int* __restrict__ esrc, const int* __restrict__ lg_src, int E) {
    int e = blockIdx.x * 4 + (threadIdx.x >> 6);
    if (e >= E) return;
    int t4 = (threadIdx.x & 63) * 4;
    int s  = g_row_ptr[e];
    int en = g_row_ptr[e + 1];
    long src_off = (long)esrc[e] * HDIM + t4;
    float4 acc = *(const float4*)&g_node_alpha[src_off];
    int i = s;
    for (; i + 4 <= en; i += 4) {
        int i0 = lg_src[i], i1 = lg_src[i + 1], i2 = lg_src[i + 2], i3 = lg_src[i + 3];
        float4 v0 = *(const float4*)&g_msg[(long)i0 * HDIM + t4];
        float4 v1 = *(const float4*)&g_msg[(long)i1 * HDIM + t4];
        float4 v2 = *(const float4*)&g_msg[(long)i2 * HDIM + t4];
        float4 v3 = *(const float4*)&g_msg[(long)i3 * HDIM + t4];
        acc.x += v0.x + v1.x + v2.x + v3.x;
        acc.y += v0.y + v1.y + v2.y + v3.y;
        acc.z += v0.z + v1.z + v2.z + v3.z;
        acc.w += v0.w + v1.w + v2.w + v3.w;
    }
    if (i < en) {
        int i0 = lg_src[i];
        int i1 = (i + 1 < en) ? lg_src[i + 1] : -1;
        int i2 = (i + 2 < en) ? lg_src[i + 2] : -1;
        float4 v0 = *(const float4*)&g_msg[(long)i0 * HDIM + t4];
        acc.x += v0.x; acc.y += v0.y; acc.z += v0.z; acc.w += v0.w;
        if (i1 >= 0) {
            float4 v = *(const float4*)&g_msg[(long)i1 * HDIM + t4];
            acc.x += v.x; acc.y += v.y; acc.z += v.z; acc.w += v.w;
        }
        if (i2 >= 0) {
            float4 v = *(const float4*)&g_msg[(long)i2 * HDIM + t4];
            acc.x += v.x; acc.y += v.y; acc.z += v.z; acc.w += v.w;
        }
    }
    *(float4*)&g_tmp[(long)e * HDIM + t4] = acc;
}

// ---------------- tf32 tensor-core GEMM: BM=64, BN=256, BK=16 ----------------
#define APAD 20
#define BPAD 264

// msg_input = [x_nodes[src] | x_edges] @ W_i ; msg = relu(msg_input). K=40 -> 3 tiles of 16
__global__ __launch_bounds__(256)
void k_edge_tf32(const float* __restrict__ x_nodes, const float* __restrict__ x_edges,
                 const float* __restrict__ W_i, const int* __restrict__ esrc, int E) {
    __shared__ unsigned As[2][64][APAD];
    __shared__ unsigned Bs[2][16][BPAD];
    int tid = threadIdx.x;
    int lane = tid & 31, wid = tid >> 5;
    int gg = lane >> 2, tig = lane & 3;
    int wm = (wid & 1) * 32, wn = (wid >> 1) * 64;
    long row0 = (long)blockIdx.x * 64;

    float c[2][8][4];
#pragma unroll
    for (int mt = 0; mt < 2; mt++)
#pragma unroll
        for (int nt = 0; nt < 8; nt++)
#pragma unroll
            for (int r = 0; r < 4; r++) c[mt][nt][r] = 0.f;

    const int NT = 3;  // 48 >= 40
    {
#pragma unroll
        for (int u = 0; u < 4; u++) {
            int i = tid + u * 256;
            int row = i >> 4, kk = i & 15;
            long r = row0 + row;
            float v = 0.f;
            if (r < E && kk < 40)
                v = (kk < 35) ? x_nodes[(long)esrc[r] * 35 + kk] : x_edges[r * 5 + (kk - 35)];
            As[0][row][kk] = f2tf(v);
        }
#pragma unroll
        for (int u = 0; u < 4; u++) {
            int ff = tid + u * 256, krow = ff >> 6, cc = ff & 63;
            float4 bvv = make_float4(0, 0, 0, 0);
            if (krow < 40) bvv = *(const float4*)&W_i[krow * 256 + cc * 4];
            unsigned* q = &Bs[0][krow][cc * 4];
            q[0] = f2tf(bvv.x); q[1] = f2tf(bvv.y); q[2] = f2tf(bvv.z); q[3] = f2tf(bvv.w);
        }
    }
    __syncthreads();

    for (int kt = 0; kt < NT; kt++) {
        int cbuf = kt & 1, nbuf = cbuf ^ 1;
        float avs[4]; float4 bv[4];
        if (kt < NT - 1) {
            int k0 = (kt + 1) * 16;
#pragma unroll
            for (int u = 0; u < 4; u++) {
                int i = tid + u * 256;
                int row = i >> 4, kk = i & 15;
                long r = row0 + row; int gk = k0 + kk;
                float v = 0.f;
                if (r < E && gk < 40)
                    v = (gk < 35) ? x_nodes[(long)esrc[r] * 35 + gk] : x_edges[r * 5 + (gk - 35)];
                avs[u] = v;
            }
#pragma unroll
            for (int u = 0; u < 4; u++) {
                int ff = tid + u * 256, krow = ff >> 6, cc = ff & 63;
                int gk = k0 + krow;
                bv[u] = make_float4(0, 0, 0, 0);
                if (gk < 40) bv[u] = *(const float4*)&W_i[gk * 256 + cc * 4];
            }
        }
#pragma unroll
        for (int ks = 0; ks < 16; ks += 8) {
            unsigned a[2][4], b[8][2];
#pragma unroll
            for (int mt = 0; mt < 2; mt++) {
                int m0 = wm + mt * 16 + gg;
                a[mt][0] = As[cbuf][m0][ks + tig];
                a[mt][1] = As[cbuf][m0 + 8][ks + tig];
                a[mt][2] = As[cbuf][m0][ks + tig + 4];
                a[mt][3] = As[cbuf][m0 + 8][ks + tig + 4];
            }
#pragma unroll
            for (int nt = 0; nt < 8; nt++) {
                int n0 = wn + nt * 8 + gg;
                b[nt][0] = Bs[cbuf][ks + tig][n0];
                b[nt][1] = Bs[cbuf][ks + tig + 4][n0];
            }
#pragma unroll
            for (int mt = 0; mt < 2; mt++)
#pragma unroll
                for (int nt = 0; nt < 8; nt++)
                    mma_tf32(c[mt][nt], a[mt], b[nt]);
        }
        if (kt < NT - 1) {
#pragma unroll
            for (int u = 0; u < 4; u++) {
                int i = tid + u * 256;
                int row = i >> 4, kk = i & 15;
                As[nbuf][row][kk] = f2tf(avs[u]);
            }
#pragma unroll
            for (int u = 0; u < 4; u++) {
                int ff = tid + u * 256, krow = ff >> 6, cc = ff & 63;
                unsigned* q = &Bs[nbuf][krow][cc * 4];
                q[0] = f2tf(bv[u].x); q[1] = f2tf(bv[u].y); q[2] = f2tf(bv[u].z); q[3] = f2tf(bv[u].w);
            }
        }
        __syncthreads();
    }

#pragma unroll
    for (int mt = 0; mt < 2; mt++) {
#pragma unroll
        for (int nt = 0; nt < 8; nt++) {
            int col = wn + nt * 8 + tig * 2;
            long r0 = row0 + wm + mt * 16 + gg;
            if (r0 < E) {
                float2 v = make_float2(c[mt][nt][0], c[mt][nt][1]);
                *(float2*)&g_msg_input[r0 * 256 + col] = v;
                float2 o = make_float2(fmaxf(v.x, 0.f), fmaxf(v.y, 0.f));
                *(float2*)&g_msg[r0 * 256 + col] = o;
            }
            long r1 = r0 + 8;
            if (r1 < E) {
                float2 v = make_float2(c[mt][nt][2], c[mt][nt][3]);
                *(float2*)&g_msg_input[r1 * 256 + col] = v;
                float2 o = make_float2(fmaxf(v.x, 0.f), fmaxf(v.y, 0.f));
                *(float2*)&g_msg[r1 * 256 + col] = o;
            }
        }
    }
}

// msg = relu(msg_input + tmp @ W_h)
__global__ __launch_bounds__(256)
void k_bp_tf32(const float* __restrict__ W_h, int E) {
    __shared__ unsigned As[2][64][APAD];
    __shared__ unsigned Bs[2][16][BPAD];
    int tid = threadIdx.x;
    int lane = tid & 31, wid = tid >> 5;
    int gg = lane >> 2, tig = lane & 3;
    int wm = (wid & 1) * 32, wn = (wid >> 1) * 64;
    long row0 = (long)blockIdx.x * 64;

    float c[2][8][4];
#pragma unroll
    for (int mt = 0; mt < 2; mt++)
#pragma unroll
        for (int nt = 0; nt < 8; nt++)
#pragma unroll
            for (int r = 0; r < 4; r++) c[mt][nt][r] = 0.f;

    {
        int f = tid, row = f >> 2, c4 = f & 3;
        long r = row0 + row;
        float4 av = make_float4(0, 0, 0, 0);
        if (r < E) av = *(const float4*)&g_tmp[r * 256 + c4 * 4];
        unsigned* p = &As[0][row][c4 * 4];
        p[0] = f2tf(av.x); p[1] = f2tf(av.y); p[2] = f2tf(av.z); p[3] = f2tf(av.w);
#pragma unroll
        for (int u = 0; u < 4; u++) {
            int ff = tid + u * 256, krow = ff >> 6, cc = ff & 63;
            float4 bv = *(const float4*)&W_h[krow * 256 + cc * 4];
            unsigned* q = &Bs[0][krow][cc * 4];
            q[0] = f2tf(bv.x); q[1] = f2tf(bv.y); q[2] = f2tf(bv.z); q[3] = f2tf(bv.w);
        }
    }
    __syncthreads();

    for (int kt = 0; kt < 16; kt++) {
        int cbuf = kt & 1, nbuf = cbuf ^ 1;
        float4 av; float4 bv[4];
        if (kt < 15) {
            int k0 = (kt + 1) * 16;
            int f = tid, row = f >> 2, c4 = f & 3;
            long r = row0 + row;
            av = make_float4(0, 0, 0, 0);
            if (r < E) av = *(const float4*)&g_tmp[r * 256 + k0 + c4 * 4];
#pragma unroll
            for (int u = 0; u < 4; u++) {
                int ff = tid + u * 256, krow = ff >> 6, cc = ff & 63;
                bv[u] = *(const float4*)&W_h[(k0 + krow) * 256 + cc * 4];
            }
        }
#pragma unroll
        for (int ks = 0; ks < 16; ks += 8) {
            unsigned a[2][4], b[8][2];
#pragma unroll
            for (int mt = 0; mt < 2; mt++) {
                int m0 = wm + mt * 16 + gg;
                a[mt][0] = As[cbuf][m0][ks + tig];
                a[mt][1] = As[cbuf][m0 + 8][ks + tig];
                a[mt][2] = As[cbuf][m0][ks + tig + 4];
                a[mt][3] = As[cbuf][m0 + 8][ks + tig + 4];
            }
#pragma unroll
            for (int nt = 0; nt < 8; nt++) {
                int n0 = wn + nt * 8 + gg;
                b[nt][0] = Bs[cbuf][ks + tig][n0];
                b[nt][1] = Bs[cbuf][ks + tig + 4][n0];
            }
#pragma unroll
            for (int mt = 0; mt < 2; mt++)
#pragma unroll
                for (int nt = 0; nt < 8; nt++)
                    mma_tf32(c[mt][nt], a[mt], b[nt]);
        }
        if (kt < 15) {
            int f = tid, row = f >> 2, c4 = f & 3;
            unsigned* p = &As[nbuf][row][c4 * 4];
            p[0] = f2tf(av.x); p[1] = f2tf(av.y); p[2] = f2tf(av.z); p[3] = f2tf(av.w);
#pragma unroll
            for (int u = 0; u < 4; u++) {
                int ff = tid + u * 256, krow = ff >> 6, cc = ff & 63;
                unsigned* q = &Bs[nbuf][krow][cc * 4];
                q[0] = f2tf(bv[u].x); q[1] = f2tf(bv[u].y); q[2] = f2tf(bv[u].z); q[3] = f2tf(bv[u].w);
            }
        }
        __syncthreads();
    }

#pragma unroll
    for (int mt = 0; mt < 2; mt++) {
#pragma unroll
        for (int nt = 0; nt < 8; nt++) {
            int col = wn + nt * 8 + tig * 2;
            long r0 = row0 + wm + mt * 16 + gg;
            if (r0 < E) {
                float2 mi = *(const float2*)&g_msg_input[r0 * 256 + col];
                float2 o;
                o.x = fmaxf(mi.x + c[mt][nt][0], 0.f);
                o.y = fmaxf(mi.y + c[mt][nt][1], 0.f);
                *(float2*)&g_msg[r0 * 256 + col] = o;
            }
            long r1 = r0 + 8;
            if (r1 < E) {
                float2 mi = *(const float2*)&g_msg_input[r1 * 256 + col];
                float2 o;
                o.x = fmaxf(mi.x + c[mt][nt][2], 0.f);
                o.y = fmaxf(mi.y + c[mt][nt][3], 0.f);
                *(float2*)&g_msg[r1 * 256 + col] = o;
            }
        }
    }
}

// h = relu([x_nodes | m] @ W_o + b_o), K=291 padded to 304
__global__ __launch_bounds__(256)
void k_out_tf32(const float* __restrict__ x_nodes, const float* __restrict__ W_o,
                const float* __restrict__ b_o, int N) {
    __shared__ unsigned As[2][64][APAD];
    __shared__ unsigned Bs[2][16][BPAD];
    int tid = threadIdx.x;
    int lane = tid & 31, wid = tid >> 5;
    int gg = lane >> 2, tig = lane & 3;
    int wm = (wid & 1) * 32, wn = (wid >> 1) * 64;
    long row0 = (long)blockIdx.x * 64;

    float c[2][8][4];
#pragma unroll
    for (int mt = 0; mt < 2; mt++)
#pragma unroll
        for (int nt = 0; nt < 8; nt++)
#pragma unroll
            for (int r = 0; r < 4; r++) c[mt][nt][r] = 0.f;

    const int NT = 19;
    {
#pragma unroll
        for (int u = 0; u < 4; u++) {
            int i = tid + u * 256;
            int row = i >> 4, kk = i & 15;
            long r = row0 + row;
            float v = 0.f;
            if (r < N && kk < 291)
                v = (kk < 35) ? x_nodes[r * 35 + kk] : g_m[r * 256 + (kk - 35)];
            As[0][row][kk] = f2tf(v);
        }
#pragma unroll
        for (int u = 0; u < 4; u++) {
            int ff = tid + u * 256, krow = ff >> 6, cc = ff & 63;
            float4 bvv = make_float4(0, 0, 0, 0);
            if (krow < 291) bvv = *(const float4*)&W_o[krow * 256 + cc * 4];
            unsigned* q = &Bs[0][krow][cc * 4];
            q[0] = f2tf(bvv.x); q[1] = f2tf(bvv.y); q[2] = f2tf(bvv.z); q[3] = f2tf(bvv.w);
        }
    }
    __syncthreads();

    for (int kt = 0; kt < NT; kt++) {
        int cbuf = kt & 1, nbuf = cbuf ^ 1;
        float avs[4]; float4 bv[4];
        if (kt < NT - 1) {
            int k0 = (kt + 1) * 16;
#pragma unroll
            for (int u = 0; u < 4; u++) {
                int i = tid + u * 256;
                int row = i >> 4, kk = i & 15;
                long r = row0 + row; int gk = k0 + kk;
                float v = 0.f;
                if (r < N && gk < 291)
                    v = (gk < 35) ? x_nodes[r * 35 + gk] : g_m[r * 256 + (gk - 35)];
                avs[u] = v;
            }
#pragma unroll
            for (int u = 0; u < 4; u++) {
                int ff = tid + u * 256, krow = ff >> 6, cc = ff & 63;
                int gk = k0 + krow;
                bv[u] = make_float4(0, 0, 0, 0);
                if (gk < 291) bv[u] = *(const float4*)&W_o[gk * 256 + cc * 4];
            }
        }
#pragma unroll
        for (int ks = 0; ks < 16; ks += 8) {
            unsigned a[2][4], b[8][2];
#pragma unroll
            for (int mt = 0; mt < 2; mt++) {
                int m0 = wm + mt * 16 + gg;
                a[mt][0] = As[cbuf][m0][ks + tig];
                a[mt][1] = As[cbuf][m0 + 8][ks + tig];
                a[mt][2] = As[cbuf][m0][ks + tig + 4];
                a[mt][3] = As[cbuf][m0 + 8][ks + tig + 4];
            }
#pragma unroll
            for (int nt = 0; nt < 8; nt++) {
                int n0 = wn + nt * 8 + gg;
                b[nt][0] = Bs[cbuf][ks + tig][n0];
                b[nt][1] = Bs[cbuf][ks + tig + 4][n0];
            }
#pragma unroll
            for (int mt = 0; mt < 2; mt++)
#pragma unroll
                for (int nt = 0; nt < 8; nt++)
                    mma_tf32(c[mt][nt], a[mt], b[nt]);
        }
        if (kt < NT - 1) {
#pragma unroll
            for (int u = 0; u < 4; u++) {
                int i = tid + u * 256;
                int row = i >> 4, kk = i & 15;
                As[nbuf][row][kk] = f2tf(avs[u]);
            }
#pragma unroll
            for (int u = 0; u < 4; u++) {
                int ff = tid + u * 256, krow = ff >> 6, cc = ff & 63;
                unsigned* q = &Bs[nbuf][krow][cc * 4];
                q[0] = f2tf(bv[u].x); q[1] = f2tf(bv[u].y); q[2] = f2tf(bv[u].z); q[3] = f2tf(bv[u].w);
            }
        }
        __syncthreads();
    }

#pragma unroll
    for (int mt = 0; mt < 2; mt++) {
#pragma unroll
        for (int nt = 0; nt < 8; nt++) {
            int col = wn + nt * 8 + tig * 2;
            float b0v = b_o[col], b1v = b_o[col + 1];
            long r0 = row0 + wm + mt * 16 + gg;
            if (r0 < N) {
                float2 o;
                o.x = fmaxf(c[mt][nt][0] + b0v, 0.f);
                o.y = fmaxf(c[mt][nt][1] + b1v, 0.f);
                *(float2*)&g_h[r0 * 256 + col] = o;
            }
            long r1 = r0 + 8;
            if (r1 < N) {
                float2 o;
                o.x = fmaxf(c[mt][nt][2] + b0v, 0.f);
                o.y = fmaxf(c[mt][nt][3] + b1v, 0.f);
                *(float2*)&g_h[r1 * 256 + col] = o;
            }
        }
    }
}

// per-graph mean over sorted graph_ids
__global__ void k_mean(const int* __restrict__ gid, float* __restrict__ out, int N) {
    int g = blockIdx.x;
    int t = threadIdx.x;
    int lo = 0, hi = N;
    while (lo < hi) { int m = (lo + hi) >> 1; if (gid[m] < g) lo = m + 1; else hi = m; }
    int s = lo;
    hi = N;
    while (lo < hi) { int m = (lo + hi) >> 1; if (gid[m] < g + 1) lo = m + 1; else hi = m; }
    int e = lo;
    float sum = 0.f;
    for (int n = s; n < e; n++) sum += g_h[n * HDIM + t];
    float c = (float)((e - s) > 0 ? (e - s) : 1);
    out[g * HDIM + t] = sum / c;
}

// ---------------- launcher ----------------
extern "C" void kernel_launch(void* const* d_in, const int* in_sizes, int n_in,
                              void* d_out, int out_size) {
    const float* x_nodes = (const float*)d_in[0];
    const float* x_edges = (const float*)d_in[1];
    const float* tree_m  = (const float*)d_in[2];
    const float* W_i     = (const float*)d_in[3];
    const float* W_h     = (const float*)d_in[4];
    const float* W_o     = (const float*)d_in[5];
    const float* b_o     = (const float*)d_in[6];
    const int*   esrc    = (const int*)d_in[7];
    const int*   edst    = (const int*)d_in[8];
    const int*   lg_src  = (const int*)d_in[9];
    const int*   lg_dst  = (const int*)d_in[10];
    const int*   tgt     = (const int*)d_in[11];
    const int*   teid    = (const int*)d_in[12];
    const int*   gid     = (const int*)d_in[13];

    int N = in_sizes[0] / 35;
    int E = in_sizes[1] / 5;
    int L = in_sizes[9];
    int K = in_sizes[11];
    int G = out_size / HDIM;
    float* out = (float*)d_out;

    k_zero_alpha<<<(N * HDIM + 255) / 256, 256>>>(N * HDIM);
    k_build_ptr<<<(E + 1 + 255) / 256, 256>>>(lg_dst, L, E);
    k_edge_tf32<<<(E + 63) / 64, 256>>>(x_nodes, x_edges, W_i, esrc, E);
    k_scatter_alpha<<<(K * 256 + 255) / 256, 256>>>(tree_m, tgt, teid, K);

    for (int it = 0; it < 3; it++) {
        k_gather<<<(E + 3) / 4, 256>>>(esrc, lg_src, E);
        k_bp_tf32<<<(E + 63) / 64, 256>>>(W_h, E);
    }

    k_copy_alpha_to_m<<<(N * HDIM + 255) / 256, 256>>>(N * HDIM);
    k_scatter_m<<<(E * 256 + 255) / 256, 256>>>(edst, E);
    k_out_tf32<<<(N + 63) / 64, 256>>>(x_nodes, W_o, b_o, N);
    k_mean<<<G, 256>>>(gid, out, N);
}